// round 1
// baseline (speedup 1.0000x reference)
#include <cuda_runtime.h>

#define BB  256
#define TT  1024
#define NUM 126
#define L   128

__global__ __launch_bounds__(128) void crf_fwd_kernel(
    const float* __restrict__ logits,     // [B, T, NUM]
    const int*   __restrict__ labels,     // [B, T]
    const int*   __restrict__ lens,       // [B]
    const float* __restrict__ trans,      // [L, L]
    float*       __restrict__ out)        // [B]
{
    const int b    = blockIdx.x;
    const int j    = threadIdx.x;        // state index 0..127
    const int warp = j >> 5;
    const int lane = j & 31;
    const int len  = lens[b];

    __shared__ float v[2][L];
    __shared__ float wred[2][4];
    __shared__ float sred[4];

    // ---- precompute E[j][i] = exp(trans[j][i]) into registers ----
    float E[L];
    #pragma unroll
    for (int i = 0; i < L; ++i) E[i] = __expf(trans[j * L + i]);

    // ---- gold score (cooperative over time) ----
    const int*   lab_b = labels + b * TT;
    const float* log_b = logits + (size_t)b * TT * NUM;

    float g = 0.f;
    for (int t = j; t < len; t += L) {
        int lab = lab_b[t];
        g += log_b[(size_t)t * NUM + lab];               // unary
        if (t > 0) g += trans[lab * L + lab_b[t - 1]];   // binary
    }
    if (j == 0) {
        g += trans[lab_b[0] * L + (L - 2)];              // start -> labels[0]
        g += trans[(L - 1) * L + lab_b[len - 1]];        // labels[len-1] -> end
    }
    #pragma unroll
    for (int o = 16; o; o >>= 1) g += __shfl_xor_sync(0xffffffffu, g, o);
    if (lane == 0) sred[warp] = g;
    __syncthreads();
    const float gold = sred[0] + sred[1] + sred[2] + sred[3];

    // ---- forward recursion: alpha[j] lives in this thread's register ----
    float alpha  = (j == L - 2) ? 0.f : -100.f;
    float lg_cur = (j < NUM) ? log_b[j] : -1000.f;

    int p = 0;
    for (int t = 0; t < len; ++t) {
        // prefetch next step's logit (latency hidden under this step's FMAs)
        float lg_next = -1000.f;
        if (j < NUM && t + 1 < len)
            lg_next = log_b[(size_t)(t + 1) * NUM + j];

        // block max of alpha
        float m = alpha;
        #pragma unroll
        for (int o = 16; o; o >>= 1)
            m = fmaxf(m, __shfl_xor_sync(0xffffffffu, m, o));
        if (lane == 0) wred[p][warp] = m;
        __syncthreads();
        m = fmaxf(fmaxf(wred[p][0], wred[p][1]), fmaxf(wred[p][2], wred[p][3]));

        v[p][j] = __expf(alpha - m);
        __syncthreads();

        // S = dot(E[j][:], v)  — v reads are warp-broadcast (conflict-free)
        float s0 = 0.f, s1 = 0.f, s2 = 0.f, s3 = 0.f;
        const float4* v4 = (const float4*)v[p];
        #pragma unroll
        for (int i = 0; i < L / 4; ++i) {
            float4 x = v4[i];
            s0 = fmaf(E[4 * i + 0], x.x, s0);
            s1 = fmaf(E[4 * i + 1], x.y, s1);
            s2 = fmaf(E[4 * i + 2], x.z, s2);
            s3 = fmaf(E[4 * i + 3], x.w, s3);
        }
        float S = (s0 + s1) + (s2 + s3);

        alpha  = lg_cur + m + __logf(S);
        lg_cur = lg_next;
        p ^= 1;
    }

    // ---- finalize: alpha += trans[end][j]; norm = logsumexp(alpha) ----
    alpha += trans[(L - 1) * L + j];

    float m = alpha;
    #pragma unroll
    for (int o = 16; o; o >>= 1)
        m = fmaxf(m, __shfl_xor_sync(0xffffffffu, m, o));
    if (lane == 0) wred[0][warp] = m;
    __syncthreads();
    m = fmaxf(fmaxf(wred[0][0], wred[0][1]), fmaxf(wred[0][2], wred[0][3]));

    float e = __expf(alpha - m);
    #pragma unroll
    for (int o = 16; o; o >>= 1) e += __shfl_xor_sync(0xffffffffu, e, o);
    if (lane == 0) sred[warp] = e;
    __syncthreads();

    if (j == 0) {
        float S = sred[0] + sred[1] + sred[2] + sred[3];
        out[b] = gold - (m + __logf(S));
    }
}

extern "C" void kernel_launch(void* const* d_in, const int* in_sizes, int n_in,
                              void* d_out, int out_size)
{
    const float* logits = (const float*)d_in[0];
    const int*   labels = (const int*)  d_in[1];
    const int*   lens   = (const int*)  d_in[2];
    const float* trans  = (const float*)d_in[3];
    float*       out    = (float*)d_out;

    crf_fwd_kernel<<<BB, L>>>(logits, labels, lens, trans, out);
}

// round 2
// speedup vs baseline: 1.7157x; 1.7157x over previous
#include <cuda_runtime.h>

#define BB  256
#define TT  1024
#define NUM 126
#define L   128

// monotone float -> uint key (order-preserving), and inverse
__device__ __forceinline__ unsigned fkey(float f) {
    int b = __float_as_int(f);
    return (unsigned)(b >= 0 ? (b ^ 0x80000000) : ~b);
}
__device__ __forceinline__ float finv(unsigned k) {
    int b = (k & 0x80000000u) ? (int)(k ^ 0x80000000u) : ~(int)k;
    return __int_as_float(b);
}

__global__ __launch_bounds__(128) void crf_fwd_kernel(
    const float* __restrict__ logits,     // [B, T, NUM]
    const int*   __restrict__ labels,     // [B, T]
    const int*   __restrict__ lens,       // [B]
    const float* __restrict__ trans,      // [L, L]
    float*       __restrict__ out)        // [B]
{
    const int b    = blockIdx.x;
    const int j    = threadIdx.x;        // state index 0..127
    const int warp = j >> 5;
    const int lane = j & 31;
    const int len  = lens[b];

    __shared__ __align__(16) float v[2][L];
    __shared__ float wmax[2][4];
    __shared__ float sred[4];

    // ---- E2[i] = packed f32x2 { exp(trans[j][2i]), exp(trans[j][2i+1]) } ----
    unsigned long long E2[L / 2];
    #pragma unroll
    for (int i = 0; i < L / 2; ++i) {
        float lo = __expf(trans[j * L + 2 * i]);
        float hi = __expf(trans[j * L + 2 * i + 1]);
        asm("mov.b64 %0, {%1, %2};" : "=l"(E2[i]) : "f"(lo), "f"(hi));
    }

    // ---- gold score (cooperative over time) ----
    const int*   lab_b = labels + b * TT;
    const float* log_b = logits + (size_t)b * TT * NUM;

    float g = 0.f;
    for (int t = j; t < len; t += L) {
        int lab = lab_b[t];
        g += log_b[(size_t)t * NUM + lab];               // unary
        if (t > 0) g += trans[lab * L + lab_b[t - 1]];   // binary
    }
    if (j == 0) {
        g += trans[lab_b[0] * L + (L - 2)];              // start -> labels[0]
        g += trans[(L - 1) * L + lab_b[len - 1]];        // labels[len-1] -> end
    }
    #pragma unroll
    for (int o = 16; o; o >>= 1) g += __shfl_xor_sync(0xffffffffu, g, o);
    if (lane == 0) sred[warp] = g;
    __syncthreads();
    const float gold = sred[0] + sred[1] + sred[2] + sred[3];

    // ---- forward recursion: alpha[j] lives in this thread's register ----
    float alpha  = (j == L - 2) ? 0.f : -100.f;
    float lg_cur = (j < NUM) ? log_b[j] : -1000.f;

    int p = 0;
    for (int t = 0; t < len; ++t) {
        // prefetch next step's logit (hidden under > 1 full step of latency)
        float lg_next = -1000.f;
        if (j < NUM && t + 1 < len)
            lg_next = log_b[(size_t)(t + 1) * NUM + j];

        // per-warp max only (single redux instead of 5-shfl tree)
        float mw = finv(__reduce_max_sync(0xffffffffu, fkey(alpha)));
        v[p][j] = __expf(alpha - mw);
        if (lane == 0) wmax[p][warp] = mw;
        __syncthreads();                                  // ONE barrier / step

        // global max + per-warp rescale factors (independent of dot loop)
        float mw4[4];
        mw4[0] = wmax[p][0]; mw4[1] = wmax[p][1];
        mw4[2] = wmax[p][2]; mw4[3] = wmax[p][3];
        const float mg = fmaxf(fmaxf(mw4[0], mw4[1]), fmaxf(mw4[2], mw4[3]));

        // S_j = sum_w exp(m_w - m_g) * sum_{i in warp w} E[j][i] * v[i]
        const ulonglong2* v2 = (const ulonglong2*)v[p];
        float S = 0.f;
        #pragma unroll
        for (int w = 0; w < 4; ++w) {
            unsigned long long a0 = 0ull, a1 = 0ull;      // packed f32x2 accumulators
            #pragma unroll
            for (int i = 0; i < 8; ++i) {
                ulonglong2 x = v2[w * 8 + i];
                asm("fma.rn.f32x2 %0, %1, %2, %0;" : "+l"(a0)
                    : "l"(E2[w * 16 + 2 * i]),     "l"(x.x));
                asm("fma.rn.f32x2 %0, %1, %2, %0;" : "+l"(a1)
                    : "l"(E2[w * 16 + 2 * i + 1]), "l"(x.y));
            }
            unsigned long long a;
            asm("add.rn.f32x2 %0, %1, %2;" : "=l"(a) : "l"(a0), "l"(a1));
            float plo, phi;
            asm("mov.b64 {%0, %1}, %2;" : "=f"(plo), "=f"(phi) : "l"(a));
            S = fmaf(__expf(mw4[w] - mg), plo + phi, S);
        }

        alpha  = lg_cur + mg + __logf(S);
        lg_cur = lg_next;
        p ^= 1;
    }

    // ---- finalize: alpha += trans[end][j]; norm = logsumexp(alpha) ----
    alpha += trans[(L - 1) * L + j];

    float mw = finv(__reduce_max_sync(0xffffffffu, fkey(alpha)));
    if (lane == 0) wmax[0][warp] = mw;
    __syncthreads();
    const float mg = fmaxf(fmaxf(wmax[0][0], wmax[0][1]),
                           fmaxf(wmax[0][2], wmax[0][3]));

    float e = __expf(alpha - mg);
    #pragma unroll
    for (int o = 16; o; o >>= 1) e += __shfl_xor_sync(0xffffffffu, e, o);
    if (lane == 0) sred[warp] = e;
    __syncthreads();

    if (j == 0) {
        float S = sred[0] + sred[1] + sred[2] + sred[3];
        out[b] = gold - (mg + __logf(S));
    }
}

extern "C" void kernel_launch(void* const* d_in, const int* in_sizes, int n_in,
                              void* d_out, int out_size)
{
    const float* logits = (const float*)d_in[0];
    const int*   labels = (const int*)  d_in[1];
    const int*   lens   = (const int*)  d_in[2];
    const float* trans  = (const float*)d_in[3];
    float*       out    = (float*)d_out;

    crf_fwd_kernel<<<BB, L>>>(logits, labels, lens, trans, out);
}